// round 14
// baseline (speedup 1.0000x reference)
#include <cuda_runtime.h>
#include <cuda_bf16.h>
#include <math.h>
#include <stdint.h>

#define N_NODES 50000
#define M_PAD   50048          // 391 * 128
#define M_HALF_BLKS 196        // row blocks in first half (rows [0, 25088))
#define E_EDGES 800000
#define NFEAT   512
#define NHID    256
#define NCLASS  64

// fp32 scratch
__device__ float g_hw2[N_NODES * NCLASS]; // relu(h+b1) @ W2
__device__ float g_h2 [N_NODES * NCLASS]; // spmm1 output

// bf16 split operands:  A' = [Ah | Al] (2K),  B't = [Bh | Bh | Bl] (3K, n-major)
__device__ __nv_bfloat16 g_A1[(size_t)M_PAD * (2 * NFEAT)];
__device__ __nv_bfloat16 g_B1[(size_t)NHID  * (3 * NFEAT)];
__device__ __nv_bfloat16 g_A2[(size_t)M_PAD * (2 * NHID)];   // rows >= N_NODES stay 0
__device__ __nv_bfloat16 g_B2[(size_t)NCLASS * (3 * NHID)];
__device__ float g_xw1[N_NODES * NHID];   // x @ W1 (fp32)

// CSR scratch (built on device every call)
__device__ int  g_cnt0[N_NODES];
__device__ int  g_cnt1[N_NODES];
__device__ int  g_ptr0[N_NODES + 1];
__device__ int  g_ptr1[N_NODES + 1];
__device__ int  g_slot0[E_EDGES];
__device__ int  g_slot1[E_EDGES];
__device__ int2 g_e0[E_EDGES];   // (col, val bits), grouped by row
__device__ int2 g_e1[E_EDGES];

// ---------------------------------------------------------------------------
// CSR build
// ---------------------------------------------------------------------------
__global__ void csr_zero() {
    int i = blockIdx.x * blockDim.x + threadIdx.x;
    if (i < N_NODES) { g_cnt0[i] = 0; g_cnt1[i] = 0; }
}

__global__ void csr_hist(const int* __restrict__ r0, const int* __restrict__ r1) {
    int i = blockIdx.x * blockDim.x + threadIdx.x;
    if (i < E_EDGES) {
        g_slot0[i] = atomicAdd(&g_cnt0[r0[i]], 1);
    } else if (i < 2 * E_EDGES) {
        int e = i - E_EDGES;
        g_slot1[e] = atomicAdd(&g_cnt1[r1[e]], 1);
    }
}

__global__ __launch_bounds__(1024) void csr_scan() {
    const int* cnt = blockIdx.x == 0 ? g_cnt0 : g_cnt1;
    int* ptr = blockIdx.x == 0 ? g_ptr0 : g_ptr1;
    __shared__ int tmp[1024];
    const int tid = threadIdx.x;
    const int chunk = (N_NODES + 1023) / 1024;   // 49
    int start = tid * chunk;
    int end   = start + chunk; if (end > N_NODES) end = N_NODES;
    int s = 0;
    for (int i = start; i < end; i++) s += cnt[i];
    tmp[tid] = s;
    __syncthreads();
    for (int d = 1; d < 1024; d <<= 1) {
        int t = (tid >= d) ? tmp[tid - d] : 0;
        __syncthreads();
        tmp[tid] += t;
        __syncthreads();
    }
    int off = tmp[tid] - s;
    for (int i = start; i < end; i++) {
        ptr[i] = off;
        off += cnt[i];
    }
    if (tid == 1023) ptr[N_NODES] = tmp[1023];
}

__global__ void csr_scatter(
    const int* __restrict__ r0, const int* __restrict__ c0, const float* __restrict__ v0,
    const int* __restrict__ r1, const int* __restrict__ c1, const float* __restrict__ v1)
{
    int i = blockIdx.x * blockDim.x + threadIdx.x;
    if (i < E_EDGES) {
        int p = g_ptr0[r0[i]] + g_slot0[i];
        g_e0[p] = make_int2(c0[i], __float_as_int(v0[i]));
    } else if (i < 2 * E_EDGES) {
        int e = i - E_EDGES;
        int p = g_ptr1[r1[e]] + g_slot1[e];
        g_e1[p] = make_int2(c1[e], __float_as_int(v1[e]));
    }
}

// ---------------------------------------------------------------------------
// Split fp32 matrix -> bf16 [Ah | Al]  (x input only), row stride 2K
// ---------------------------------------------------------------------------
__global__ __launch_bounds__(256) void conv_split_x(
    const float* __restrict__ src, __nv_bfloat16* __restrict__ dst,
    int Msrc, int K)
{
    long idx = (long)blockIdx.x * blockDim.x + threadIdx.x;
    long total = (long)M_PAD * (K / 4);
    if (idx >= total) return;
    int r  = (int)(idx / (K / 4));
    int k4 = (int)(idx % (K / 4)) * 4;

    float4 v = make_float4(0.f, 0.f, 0.f, 0.f);
    if (r < Msrc) v = *(const float4*)(src + (size_t)r * K + k4);
    float a[4] = {v.x, v.y, v.z, v.w};
    unsigned long long ph = 0, pl = 0;
    #pragma unroll
    for (int i = 0; i < 4; i++) {
        __nv_bfloat16 h = __float2bfloat16(a[i]);
        __nv_bfloat16 l = __float2bfloat16(a[i] - __bfloat162float(h));
        ph |= (unsigned long long)__bfloat16_as_ushort(h) << (16 * i);
        pl |= (unsigned long long)__bfloat16_as_ushort(l) << (16 * i);
    }
    __nv_bfloat16* row = dst + (size_t)r * 2 * K;
    *(unsigned long long*)(row + k4)     = ph;
    *(unsigned long long*)(row + K + k4) = pl;
}

// ---------------------------------------------------------------------------
// Split weight W[K][N] (row-major) -> Bt[N][3K] bf16 = [Bh | Bh | Bl]
// ---------------------------------------------------------------------------
__global__ __launch_bounds__(256) void conv_w(
    const float* __restrict__ W, __nv_bfloat16* __restrict__ Bt, int K, int N)
{
    int idx = blockIdx.x * blockDim.x + threadIdx.x;
    if (idx >= K * N) return;
    int n = idx / K, k = idx % K;
    float w = W[(size_t)k * N + n];
    __nv_bfloat16 h = __float2bfloat16(w);
    __nv_bfloat16 l = __float2bfloat16(w - __bfloat162float(h));
    __nv_bfloat16* row = Bt + (size_t)n * 3 * K;
    row[k]         = h;
    row[K + k]     = h;
    row[2 * K + k] = l;
}

// ---------------------------------------------------------------------------
// bf16 tensor-core GEMM: C = A([Ah|Al], stride KpA) @ Bt([Bh|Bh|Bl], stride Kp)^T
// Loop over Kp chunks; A address wraps (3rd segment re-reads Ah).
// 128 x BTN block tile, 8 warps, K-step 64, 2-stage cp.async, 2 CTAs/SM.
// rowBase: row-block offset (for half launches).
// ---------------------------------------------------------------------------
__device__ __forceinline__ void cp16(uint32_t dst_smem, const void* src) {
    asm volatile("cp.async.cg.shared.global [%0], [%1], 16;"
                 :: "r"(dst_smem), "l"(src));
}

__device__ __forceinline__ void ldm_x4(uint32_t r[4], uint32_t addr) {
    asm volatile("ldmatrix.sync.aligned.m8n8.x4.shared.b16 {%0,%1,%2,%3}, [%4];"
                 : "=r"(r[0]), "=r"(r[1]), "=r"(r[2]), "=r"(r[3]) : "r"(addr));
}

__device__ __forceinline__ void mma_bf16(float c[4],
    uint32_t a0, uint32_t a1, uint32_t a2, uint32_t a3,
    uint32_t b0, uint32_t b1)
{
    asm volatile(
        "mma.sync.aligned.m16n8k16.row.col.f32.bf16.bf16.f32 "
        "{%0,%1,%2,%3}, {%4,%5,%6,%7}, {%8,%9}, {%0,%1,%2,%3};"
        : "+f"(c[0]), "+f"(c[1]), "+f"(c[2]), "+f"(c[3])
        : "r"(a0), "r"(a1), "r"(a2), "r"(a3), "r"(b0), "r"(b1));
}

template<int BTN>
__global__ __launch_bounds__(256, 2) void bf16_gemm(
    const __nv_bfloat16* __restrict__ A, const __nv_bfloat16* __restrict__ Bt,
    float* __restrict__ C, int M, int Nc, int Kp, int KpA, int rowBase)
{
    constexpr int P = 72;                  // 144B pitch: ldmatrix conflict-free
    constexpr int ASTRIDE = 128 * P * 2;
    constexpr int BSTRIDE = BTN * P * 2;
    extern __shared__ __align__(16) char smem[];
    const uint32_t smemBase = (uint32_t)__cvta_generic_to_shared(smem);
    const uint32_t asBase = smemBase;
    const uint32_t bsBase = smemBase + 2 * ASTRIDE;

    const int tid  = threadIdx.x;
    const int warp = tid >> 5;
    const int lane = tid & 31;
    const int l4 = lane >> 2;
    const int lm = lane & 3;
    const int warpM = warp & 3;
    const int warpN = warp >> 2;
    constexpr int WN = BTN / 2;
    constexpr int NT = WN / 8;
    constexpr int NP = NT / 2;
    const int m0 = warpM * 32;
    const int n0 = warpN * WN;
    const int rowBlock = (rowBase + blockIdx.y) * 128;
    const int colBlock = blockIdx.x * BTN;

    const int aRowL = ((lane >> 3) & 1) * 8 + (lane & 7);
    const int aColH = (lane >> 4) * 8;
    uint32_t aoff[2];
    #pragma unroll
    for (int mt = 0; mt < 2; mt++)
        aoff[mt] = ((m0 + mt * 16 + aRowL) * P + aColH) * 2;
    const int bColH = ((lane >> 3) & 1) * 8;
    uint32_t boff[NP > 0 ? NP : 1];
    #pragma unroll
    for (int p = 0; p < NP; p++)
        boff[p] = ((n0 + (2 * p + (lane >> 4)) * 8 + (lane & 7)) * P + bColH) * 2;

    float acc[2][NT][4];
    #pragma unroll
    for (int mt = 0; mt < 2; mt++)
        #pragma unroll
        for (int nt = 0; nt < NT; nt++)
            #pragma unroll
            for (int j = 0; j < 4; j++) acc[mt][nt][j] = 0.f;

    auto load_stage = [&](int s, int k0) {
        int k0a = (k0 >= KpA) ? k0 - KpA : k0;   // 3rd segment re-reads Ah
        uint32_t aS = asBase + s * ASTRIDE;
        uint32_t bS = bsBase + s * BSTRIDE;
        #pragma unroll
        for (int ch = tid; ch < 1024; ch += 256) {         // A: 128 rows x 8 chunks
            int r = ch >> 3, c = ch & 7;
            cp16(aS + (r * P + c * 8) * 2,
                 A + (size_t)(rowBlock + r) * KpA + k0a + c * 8);
        }
        #pragma unroll
        for (int ch = tid; ch < BTN * 8; ch += 256) {      // B: BTN rows x 8 chunks
            int r = ch >> 3, c = ch & 7;
            cp16(bS + (r * P + c * 8) * 2,
                 Bt + (size_t)(colBlock + r) * Kp + k0 + c * 8);
        }
    };

    load_stage(0, 0);
    asm volatile("cp.async.commit_group;");
    load_stage(1, 64);
    asm volatile("cp.async.commit_group;");

    const int NCHUNK = Kp / 64;
    for (int c = 0; c < NCHUNK; c++) {
        int s = c & 1;
        asm volatile("cp.async.wait_group 1;");
        __syncthreads();

        const uint32_t aStage = asBase + s * ASTRIDE;
        const uint32_t bStage = bsBase + s * BSTRIDE;

        #pragma unroll
        for (int kk = 0; kk < 64; kk += 16) {
            uint32_t a[2][4];
            ldm_x4(a[0], aStage + aoff[0] + kk * 2);
            ldm_x4(a[1], aStage + aoff[1] + kk * 2);
            #pragma unroll
            for (int p = 0; p < NP; p++) {
                uint32_t b[4];
                ldm_x4(b, bStage + boff[p] + kk * 2);
                mma_bf16(acc[0][2*p],   a[0][0], a[0][1], a[0][2], a[0][3], b[0], b[1]);
                mma_bf16(acc[1][2*p],   a[1][0], a[1][1], a[1][2], a[1][3], b[0], b[1]);
                mma_bf16(acc[0][2*p+1], a[0][0], a[0][1], a[0][2], a[0][3], b[2], b[3]);
                mma_bf16(acc[1][2*p+1], a[1][0], a[1][1], a[1][2], a[1][3], b[2], b[3]);
            }
        }
        __syncthreads();
        if (c + 2 < NCHUNK) load_stage(s, (c + 2) * 64);
        asm volatile("cp.async.commit_group;");
    }

    #pragma unroll
    for (int mt = 0; mt < 2; mt++) {
        int r = rowBlock + m0 + mt * 16 + l4;
        #pragma unroll
        for (int nt = 0; nt < NT; nt++) {
            int c = colBlock + n0 + nt * 8 + lm * 2;
            if (r < M)
                *(float2*)(C + (size_t)r * Nc + c) =
                    make_float2(acc[mt][nt][0], acc[mt][nt][1]);
            if (r + 8 < M)
                *(float2*)(C + (size_t)(r + 8) * Nc + c) =
                    make_float2(acc[mt][nt][2], acc[mt][nt][3]);
        }
    }
}

// ---------------------------------------------------------------------------
// CSR SPMM0 + fused relu(h+b1) + bf16 split -> writes g_A2 row ([Ah|Al]).
// Row range [rowStart, rowEnd).
// ---------------------------------------------------------------------------
__global__ __launch_bounds__(256) void spmm0_csr(const float* __restrict__ b1,
                                                 int rowStart, int rowEnd)
{
    int r = rowStart + blockIdx.x * 8 + (threadIdx.x >> 5);
    if (r >= rowEnd) return;
    const int lane = threadIdx.x & 31;
    const int beg = g_ptr0[r];
    const int end = g_ptr0[r + 1];

    float4 a0 = make_float4(0.f, 0.f, 0.f, 0.f);
    float4 a1 = a0;

    int e = beg;
    for (; e + 2 <= end; e += 2) {
        int2 ea = g_e0[e], eb = g_e0[e + 1];
        float va = __int_as_float(ea.y), vb = __int_as_float(eb.y);
        const float4* sa = (const float4*)(g_xw1 + (size_t)ea.x * NHID) + lane * 2;
        const float4* sb = (const float4*)(g_xw1 + (size_t)eb.x * NHID) + lane * 2;
        float4 xa0 = sa[0], xa1 = sa[1], xb0 = sb[0], xb1 = sb[1];
        a0.x += va * xa0.x; a0.y += va * xa0.y; a0.z += va * xa0.z; a0.w += va * xa0.w;
        a1.x += va * xa1.x; a1.y += va * xa1.y; a1.z += va * xa1.z; a1.w += va * xa1.w;
        a0.x += vb * xb0.x; a0.y += vb * xb0.y; a0.z += vb * xb0.z; a0.w += vb * xb0.w;
        a1.x += vb * xb1.x; a1.y += vb * xb1.y; a1.z += vb * xb1.z; a1.w += vb * xb1.w;
    }
    if (e < end) {
        int2 ea = g_e0[e];
        float va = __int_as_float(ea.y);
        const float4* sa = (const float4*)(g_xw1 + (size_t)ea.x * NHID) + lane * 2;
        float4 xa0 = sa[0], xa1 = sa[1];
        a0.x += va * xa0.x; a0.y += va * xa0.y; a0.z += va * xa0.z; a0.w += va * xa0.w;
        a1.x += va * xa1.x; a1.y += va * xa1.y; a1.z += va * xa1.z; a1.w += va * xa1.w;
    }

    const int f = lane * 8;
    float4 bb0 = *(const float4*)(b1 + f);
    float4 bb1 = *(const float4*)(b1 + f + 4);
    float h[8];
    h[0] = fmaxf(a0.x + bb0.x, 0.f); h[1] = fmaxf(a0.y + bb0.y, 0.f);
    h[2] = fmaxf(a0.z + bb0.z, 0.f); h[3] = fmaxf(a0.w + bb0.w, 0.f);
    h[4] = fmaxf(a1.x + bb1.x, 0.f); h[5] = fmaxf(a1.y + bb1.y, 0.f);
    h[6] = fmaxf(a1.z + bb1.z, 0.f); h[7] = fmaxf(a1.w + bb1.w, 0.f);

    unsigned long long ph[2] = {0ull, 0ull}, pl[2] = {0ull, 0ull};
    #pragma unroll
    for (int i = 0; i < 8; i++) {
        __nv_bfloat16 hi = __float2bfloat16(h[i]);
        __nv_bfloat16 lo = __float2bfloat16(h[i] - __bfloat162float(hi));
        ph[i >> 2] |= (unsigned long long)__bfloat16_as_ushort(hi) << (16 * (i & 3));
        pl[i >> 2] |= (unsigned long long)__bfloat16_as_ushort(lo) << (16 * (i & 3));
    }
    __nv_bfloat16* row = g_A2 + (size_t)r * (2 * NHID) + f;
    *(unsigned long long*)(row)            = ph[0];
    *(unsigned long long*)(row + 4)        = ph[1];
    *(unsigned long long*)(row + NHID)     = pl[0];
    *(unsigned long long*)(row + NHID + 4) = pl[1];
}

// ---------------------------------------------------------------------------
// CSR SPMM1: warp per row, lane handles 2 features. Writes g_h2 directly.
// ---------------------------------------------------------------------------
__global__ __launch_bounds__(256) void spmm1_csr()
{
    int r = blockIdx.x * 8 + (threadIdx.x >> 5);
    if (r >= N_NODES) return;
    const int lane = threadIdx.x & 31;
    const int beg = g_ptr1[r];
    const int end = g_ptr1[r + 1];

    float2 acc = make_float2(0.f, 0.f);
    int e = beg;
    for (; e + 2 <= end; e += 2) {
        int2 ea = g_e1[e], eb = g_e1[e + 1];
        float va = __int_as_float(ea.y), vb = __int_as_float(eb.y);
        float2 xa = ((const float2*)(g_hw2 + (size_t)ea.x * NCLASS))[lane];
        float2 xb = ((const float2*)(g_hw2 + (size_t)eb.x * NCLASS))[lane];
        acc.x += va * xa.x; acc.y += va * xa.y;
        acc.x += vb * xb.x; acc.y += vb * xb.y;
    }
    if (e < end) {
        int2 ea = g_e1[e];
        float va = __int_as_float(ea.y);
        float2 xa = ((const float2*)(g_hw2 + (size_t)ea.x * NCLASS))[lane];
        acc.x += va * xa.x; acc.y += va * xa.y;
    }
    ((float2*)(g_h2 + (size_t)r * NCLASS))[lane] = acc;
}

// ---------------------------------------------------------------------------
// Final: logits = (h2 + b2) @ LW + Lb ; log_softmax. One warp per node.
// ---------------------------------------------------------------------------
__global__ __launch_bounds__(256) void final_kernel(
    const float* __restrict__ b2, const float* __restrict__ LW,
    const float* __restrict__ Lb, float* __restrict__ out)
{
    __shared__ float sLW[NCLASS * NCLASS];
    __shared__ float sh2[8][NCLASS];
    const int tid = threadIdx.x;
    for (int i = tid; i < NCLASS * NCLASS; i += 256) sLW[i] = LW[i];

    const int warp = tid >> 5;
    const int lane = tid & 31;
    const int node = blockIdx.x * 8 + warp;

    if (node < N_NODES) {
        sh2[warp][lane]      = g_h2[(long)node * NCLASS + lane]      + b2[lane];
        sh2[warp][lane + 32] = g_h2[(long)node * NCLASS + lane + 32] + b2[lane + 32];
    }
    __syncthreads();
    if (node >= N_NODES) return;

    float l0 = Lb[lane];
    float l1 = Lb[lane + 32];
    #pragma unroll
    for (int k = 0; k < NCLASS; k++) {
        float hv = sh2[warp][k];
        l0 += hv * sLW[k * NCLASS + lane];
        l1 += hv * sLW[k * NCLASS + lane + 32];
    }

    float m = fmaxf(l0, l1);
    #pragma unroll
    for (int off = 16; off; off >>= 1)
        m = fmaxf(m, __shfl_xor_sync(0xffffffff, m, off));
    float s = expf(l0 - m) + expf(l1 - m);
    #pragma unroll
    for (int off = 16; off; off >>= 1)
        s += __shfl_xor_sync(0xffffffff, s, off);
    float lse = m + logf(s);

    out[(long)node * NCLASS + lane]      = l0 - lse;
    out[(long)node * NCLASS + lane + 32] = l1 - lse;
}

// ---------------------------------------------------------------------------
// Launch — side stream: W1 split, CSR build, W2 split, GEMM2 half0.
// ---------------------------------------------------------------------------
extern "C" void kernel_launch(void* const* d_in, const int* in_sizes, int n_in,
                              void* d_out, int out_size)
{
    const float* x   = (const float*)d_in[0];
    const float* a0v = (const float*)d_in[1];
    const float* a1v = (const float*)d_in[2];
    const float* W1  = (const float*)d_in[3];
    const float* b1  = (const float*)d_in[4];
    const float* W2  = (const float*)d_in[5];
    const float* b2  = (const float*)d_in[6];
    const float* LW  = (const float*)d_in[7];
    const float* Lb  = (const float*)d_in[8];
    const int*   a0r = (const int*)d_in[9];
    const int*   a0c = (const int*)d_in[10];
    const int*   a1r = (const int*)d_in[11];
    const int*   a1c = (const int*)d_in[12];
    float* out = (float*)d_out;

    float *p_xw1, *p_hw2;
    __nv_bfloat16 *p_A1, *p_B1, *p_A2, *p_B2;
    cudaGetSymbolAddress((void**)&p_xw1, g_xw1);
    cudaGetSymbolAddress((void**)&p_hw2, g_hw2);
    cudaGetSymbolAddress((void**)&p_A1,  g_A1);
    cudaGetSymbolAddress((void**)&p_B1,  g_B1);
    cudaGetSymbolAddress((void**)&p_A2,  g_A2);
    cudaGetSymbolAddress((void**)&p_B2,  g_B2);

    const int SMEM1 = 2 * (128 * 72 + 128 * 72) * 2;  // 73728
    const int SMEM2 = 2 * (128 * 72 + 64 * 72) * 2;   // 55296
    cudaFuncSetAttribute(bf16_gemm<128>,
                         cudaFuncAttributeMaxDynamicSharedMemorySize, SMEM1);
    cudaFuncSetAttribute(bf16_gemm<64>,
                         cudaFuncAttributeMaxDynamicSharedMemorySize, SMEM2);

    // side stream + events (host objects; created during capture call only)
    cudaStream_t s2;
    cudaStreamCreateWithFlags(&s2, cudaStreamNonBlocking);
    cudaEvent_t evFork, evW1, evJoin, evH0, evG2h0;
    cudaEventCreateWithFlags(&evFork,  cudaEventDisableTiming);
    cudaEventCreateWithFlags(&evW1,    cudaEventDisableTiming);
    cudaEventCreateWithFlags(&evJoin,  cudaEventDisableTiming);
    cudaEventCreateWithFlags(&evH0,    cudaEventDisableTiming);
    cudaEventCreateWithFlags(&evG2h0,  cudaEventDisableTiming);

    // ---- fork ----
    cudaEventRecord(evFork, 0);
    cudaStreamWaitEvent(s2, evFork, 0);

    // ---- stream B: W1 split -> evW1 -> CSR build -> W2 split -> evJoin ----
    conv_w<<<(NFEAT * NHID + 255) / 256, 256, 0, s2>>>(W1, p_B1, NFEAT, NHID);
    cudaEventRecord(evW1, s2);
    csr_zero<<<(N_NODES + 255) / 256, 256, 0, s2>>>();
    csr_hist<<<(2 * E_EDGES + 255) / 256, 256, 0, s2>>>(a0r, a1r);
    csr_scan<<<2, 1024, 0, s2>>>();
    csr_scatter<<<(2 * E_EDGES + 255) / 256, 256, 0, s2>>>(a0r, a0c, a0v,
                                                           a1r, a1c, a1v);
    conv_w<<<(NHID * NCLASS + 255) / 256, 256, 0, s2>>>(W2, p_B2, NHID, NCLASS);
    cudaEventRecord(evJoin, s2);

    // ---- stream A (default): x split, GEMM1 ----
    {
        long total = (long)M_PAD * (NFEAT / 4);
        conv_split_x<<<(int)((total + 255) / 256), 256>>>(x, p_A1, N_NODES, NFEAT);
    }
    cudaStreamWaitEvent(0, evW1, 0);
    {
        dim3 grid(NHID / 128, M_PAD / 128);
        bf16_gemm<128><<<grid, 256, SMEM1>>>(p_A1, p_B1, p_xw1,
                                             N_NODES, NHID, 3 * NFEAT,
                                             2 * NFEAT, 0);
    }

    // ---- join CSR, then pipelined SPMM0 / GEMM2 halves ----
    cudaStreamWaitEvent(0, evJoin, 0);

    // SPMM0 half 0: rows [0, 25088)
    spmm0_csr<<<M_HALF_BLKS * 16, 256>>>(b1, 0, M_HALF_BLKS * 128);
    cudaEventRecord(evH0, 0);

    // stream B: GEMM2 half 0 (row blocks [0, 196))
    cudaStreamWaitEvent(s2, evH0, 0);
    {
        dim3 grid(1, M_HALF_BLKS);
        bf16_gemm<64><<<grid, 256, SMEM2, s2>>>(p_A2, p_B2, p_hw2,
                                                N_NODES, NCLASS, 3 * NHID,
                                                2 * NHID, 0);
    }
    cudaEventRecord(evG2h0, s2);

    // stream A: SPMM0 half 1: rows [25088, 50000)
    {
        int rows = N_NODES - M_HALF_BLKS * 128;
        spmm0_csr<<<(rows + 7) / 8, 256>>>(b1, M_HALF_BLKS * 128, N_NODES);
    }

    // GEMM2 half 1 (row blocks [196, 391))
    {
        dim3 grid(1, M_PAD / 128 - M_HALF_BLKS);
        bf16_gemm<64><<<grid, 256, SMEM2>>>(p_A2, p_B2, p_hw2,
                                            N_NODES, NCLASS, 3 * NHID,
                                            2 * NHID, M_HALF_BLKS);
    }

    // join GEMM2 half 0 before SPMM1
    cudaStreamWaitEvent(0, evG2h0, 0);

    // ---- SPMM1 (CSR) -> g_h2 ----
    spmm1_csr<<<(N_NODES + 7) / 8, 256>>>();

    // ---- Final linear + log_softmax ----
    final_kernel<<<(N_NODES + 7) / 8, 256>>>(b2, LW, Lb, out);
}

// round 15
// speedup vs baseline: 1.0030x; 1.0030x over previous
#include <cuda_runtime.h>
#include <cuda_bf16.h>
#include <math.h>
#include <stdint.h>

#define N_NODES 50000
#define M_PAD   50048          // 391 * 128
#define E_EDGES 800000
#define NFEAT   512
#define NHID    256
#define NCLASS  64

// fp32 scratch
__device__ float g_hw2[N_NODES * NCLASS]; // relu(h+b1) @ W2
__device__ float g_h2 [N_NODES * NCLASS]; // spmm1 output

// bf16 split operands:  A' = [Ah | Al] (2K),  B't = [Bh | Bh | Bl] (3K, n-major)
__device__ __nv_bfloat16 g_A1[(size_t)M_PAD * (2 * NFEAT)];
__device__ __nv_bfloat16 g_B1[(size_t)NHID  * (3 * NFEAT)];
__device__ __nv_bfloat16 g_A2[(size_t)M_PAD * (2 * NHID)];   // rows >= N_NODES stay 0
__device__ __nv_bfloat16 g_B2[(size_t)NCLASS * (3 * NHID)];
__device__ float g_xw1[N_NODES * NHID];   // x @ W1 (fp32)

// CSR scratch (built on device every call)
__device__ int  g_cnt0[N_NODES];
__device__ int  g_cnt1[N_NODES];
__device__ int  g_ptr0[N_NODES + 1];
__device__ int  g_ptr1[N_NODES + 1];
__device__ int  g_slot0[E_EDGES];
__device__ int  g_slot1[E_EDGES];
__device__ int2 g_e0[E_EDGES];   // (col, val bits), grouped by row
__device__ int2 g_e1[E_EDGES];

// ---------------------------------------------------------------------------
// CSR build
// ---------------------------------------------------------------------------
__global__ void csr_zero() {
    int i = blockIdx.x * blockDim.x + threadIdx.x;
    if (i < N_NODES) { g_cnt0[i] = 0; g_cnt1[i] = 0; }
}

__global__ void csr_hist(const int* __restrict__ r0, const int* __restrict__ r1) {
    int i = blockIdx.x * blockDim.x + threadIdx.x;
    if (i < E_EDGES) {
        g_slot0[i] = atomicAdd(&g_cnt0[r0[i]], 1);
    } else if (i < 2 * E_EDGES) {
        int e = i - E_EDGES;
        g_slot1[e] = atomicAdd(&g_cnt1[r1[e]], 1);
    }
}

__global__ __launch_bounds__(1024) void csr_scan() {
    const int* cnt = blockIdx.x == 0 ? g_cnt0 : g_cnt1;
    int* ptr = blockIdx.x == 0 ? g_ptr0 : g_ptr1;
    __shared__ int tmp[1024];
    const int tid = threadIdx.x;
    const int chunk = (N_NODES + 1023) / 1024;   // 49
    int start = tid * chunk;
    int end   = start + chunk; if (end > N_NODES) end = N_NODES;
    int s = 0;
    for (int i = start; i < end; i++) s += cnt[i];
    tmp[tid] = s;
    __syncthreads();
    for (int d = 1; d < 1024; d <<= 1) {
        int t = (tid >= d) ? tmp[tid - d] : 0;
        __syncthreads();
        tmp[tid] += t;
        __syncthreads();
    }
    int off = tmp[tid] - s;
    for (int i = start; i < end; i++) {
        ptr[i] = off;
        off += cnt[i];
    }
    if (tid == 1023) ptr[N_NODES] = tmp[1023];
}

__global__ void csr_scatter(
    const int* __restrict__ r0, const int* __restrict__ c0, const float* __restrict__ v0,
    const int* __restrict__ r1, const int* __restrict__ c1, const float* __restrict__ v1)
{
    int i = blockIdx.x * blockDim.x + threadIdx.x;
    if (i < E_EDGES) {
        int p = g_ptr0[r0[i]] + g_slot0[i];
        g_e0[p] = make_int2(c0[i], __float_as_int(v0[i]));
    } else if (i < 2 * E_EDGES) {
        int e = i - E_EDGES;
        int p = g_ptr1[r1[e]] + g_slot1[e];
        g_e1[p] = make_int2(c1[e], __float_as_int(v1[e]));
    }
}

// ---------------------------------------------------------------------------
// Split fp32 matrix -> bf16 [Ah | Al]  (x input only), row stride 2K
// ---------------------------------------------------------------------------
__global__ __launch_bounds__(256) void conv_split_x(
    const float* __restrict__ src, __nv_bfloat16* __restrict__ dst,
    int Msrc, int K)
{
    long idx = (long)blockIdx.x * blockDim.x + threadIdx.x;
    long total = (long)M_PAD * (K / 4);
    if (idx >= total) return;
    int r  = (int)(idx / (K / 4));
    int k4 = (int)(idx % (K / 4)) * 4;

    float4 v = make_float4(0.f, 0.f, 0.f, 0.f);
    if (r < Msrc) v = *(const float4*)(src + (size_t)r * K + k4);
    float a[4] = {v.x, v.y, v.z, v.w};
    unsigned long long ph = 0, pl = 0;
    #pragma unroll
    for (int i = 0; i < 4; i++) {
        __nv_bfloat16 h = __float2bfloat16(a[i]);
        __nv_bfloat16 l = __float2bfloat16(a[i] - __bfloat162float(h));
        ph |= (unsigned long long)__bfloat16_as_ushort(h) << (16 * i);
        pl |= (unsigned long long)__bfloat16_as_ushort(l) << (16 * i);
    }
    __nv_bfloat16* row = dst + (size_t)r * 2 * K;
    *(unsigned long long*)(row + k4)     = ph;
    *(unsigned long long*)(row + K + k4) = pl;
}

// ---------------------------------------------------------------------------
// Split weight W[K][N] (row-major) -> Bt[N][3K] bf16 = [Bh | Bh | Bl]
// ---------------------------------------------------------------------------
__global__ __launch_bounds__(256) void conv_w(
    const float* __restrict__ W, __nv_bfloat16* __restrict__ Bt, int K, int N)
{
    int idx = blockIdx.x * blockDim.x + threadIdx.x;
    if (idx >= K * N) return;
    int n = idx / K, k = idx % K;
    float w = W[(size_t)k * N + n];
    __nv_bfloat16 h = __float2bfloat16(w);
    __nv_bfloat16 l = __float2bfloat16(w - __bfloat162float(h));
    __nv_bfloat16* row = Bt + (size_t)n * 3 * K;
    row[k]         = h;
    row[K + k]     = h;
    row[2 * K + k] = l;
}

// ---------------------------------------------------------------------------
// bf16 tensor-core GEMM: C = A([Ah|Al], stride KpA) @ Bt([Bh|Bh|Bl], stride Kp)^T
// A address wraps (3rd K-segment re-reads Ah). 128 x BTN tile, 8 warps,
// K-step 64, 2-stage cp.async, ldmatrix.x4, 2 CTAs/SM.
// ---------------------------------------------------------------------------
__device__ __forceinline__ void cp16(uint32_t dst_smem, const void* src) {
    asm volatile("cp.async.cg.shared.global [%0], [%1], 16;"
                 :: "r"(dst_smem), "l"(src));
}

__device__ __forceinline__ void ldm_x4(uint32_t r[4], uint32_t addr) {
    asm volatile("ldmatrix.sync.aligned.m8n8.x4.shared.b16 {%0,%1,%2,%3}, [%4];"
                 : "=r"(r[0]), "=r"(r[1]), "=r"(r[2]), "=r"(r[3]) : "r"(addr));
}

__device__ __forceinline__ void mma_bf16(float c[4],
    uint32_t a0, uint32_t a1, uint32_t a2, uint32_t a3,
    uint32_t b0, uint32_t b1)
{
    asm volatile(
        "mma.sync.aligned.m16n8k16.row.col.f32.bf16.bf16.f32 "
        "{%0,%1,%2,%3}, {%4,%5,%6,%7}, {%8,%9}, {%0,%1,%2,%3};"
        : "+f"(c[0]), "+f"(c[1]), "+f"(c[2]), "+f"(c[3])
        : "r"(a0), "r"(a1), "r"(a2), "r"(a3), "r"(b0), "r"(b1));
}

template<int BTN>
__global__ __launch_bounds__(256, 2) void bf16_gemm(
    const __nv_bfloat16* __restrict__ A, const __nv_bfloat16* __restrict__ Bt,
    float* __restrict__ C, int M, int Nc, int Kp, int KpA)
{
    constexpr int P = 72;                  // 144B pitch: ldmatrix conflict-free
    constexpr int ASTRIDE = 128 * P * 2;
    constexpr int BSTRIDE = BTN * P * 2;
    extern __shared__ __align__(16) char smem[];
    const uint32_t smemBase = (uint32_t)__cvta_generic_to_shared(smem);
    const uint32_t asBase = smemBase;
    const uint32_t bsBase = smemBase + 2 * ASTRIDE;

    const int tid  = threadIdx.x;
    const int warp = tid >> 5;
    const int lane = tid & 31;
    const int l4 = lane >> 2;
    const int lm = lane & 3;
    const int warpM = warp & 3;
    const int warpN = warp >> 2;
    constexpr int WN = BTN / 2;
    constexpr int NT = WN / 8;
    constexpr int NP = NT / 2;
    const int m0 = warpM * 32;
    const int n0 = warpN * WN;
    const int rowBlock = blockIdx.y * 128;
    const int colBlock = blockIdx.x * BTN;

    const int aRowL = ((lane >> 3) & 1) * 8 + (lane & 7);
    const int aColH = (lane >> 4) * 8;
    uint32_t aoff[2];
    #pragma unroll
    for (int mt = 0; mt < 2; mt++)
        aoff[mt] = ((m0 + mt * 16 + aRowL) * P + aColH) * 2;
    const int bColH = ((lane >> 3) & 1) * 8;
    uint32_t boff[NP > 0 ? NP : 1];
    #pragma unroll
    for (int p = 0; p < NP; p++)
        boff[p] = ((n0 + (2 * p + (lane >> 4)) * 8 + (lane & 7)) * P + bColH) * 2;

    float acc[2][NT][4];
    #pragma unroll
    for (int mt = 0; mt < 2; mt++)
        #pragma unroll
        for (int nt = 0; nt < NT; nt++)
            #pragma unroll
            for (int j = 0; j < 4; j++) acc[mt][nt][j] = 0.f;

    auto load_stage = [&](int s, int k0) {
        int k0a = (k0 >= KpA) ? k0 - KpA : k0;   // 3rd segment re-reads Ah
        uint32_t aS = asBase + s * ASTRIDE;
        uint32_t bS = bsBase + s * BSTRIDE;
        #pragma unroll
        for (int ch = tid; ch < 1024; ch += 256) {         // A: 128 rows x 8 chunks
            int r = ch >> 3, c = ch & 7;
            cp16(aS + (r * P + c * 8) * 2,
                 A + (size_t)(rowBlock + r) * KpA + k0a + c * 8);
        }
        #pragma unroll
        for (int ch = tid; ch < BTN * 8; ch += 256) {      // B: BTN rows x 8 chunks
            int r = ch >> 3, c = ch & 7;
            cp16(bS + (r * P + c * 8) * 2,
                 Bt + (size_t)(colBlock + r) * Kp + k0 + c * 8);
        }
    };

    load_stage(0, 0);
    asm volatile("cp.async.commit_group;");
    load_stage(1, 64);
    asm volatile("cp.async.commit_group;");

    const int NCHUNK = Kp / 64;
    for (int c = 0; c < NCHUNK; c++) {
        int s = c & 1;
        asm volatile("cp.async.wait_group 1;");
        __syncthreads();

        const uint32_t aStage = asBase + s * ASTRIDE;
        const uint32_t bStage = bsBase + s * BSTRIDE;

        #pragma unroll
        for (int kk = 0; kk < 64; kk += 16) {
            uint32_t a[2][4];
            ldm_x4(a[0], aStage + aoff[0] + kk * 2);
            ldm_x4(a[1], aStage + aoff[1] + kk * 2);
            #pragma unroll
            for (int p = 0; p < NP; p++) {
                uint32_t b[4];
                ldm_x4(b, bStage + boff[p] + kk * 2);
                mma_bf16(acc[0][2*p],   a[0][0], a[0][1], a[0][2], a[0][3], b[0], b[1]);
                mma_bf16(acc[1][2*p],   a[1][0], a[1][1], a[1][2], a[1][3], b[0], b[1]);
                mma_bf16(acc[0][2*p+1], a[0][0], a[0][1], a[0][2], a[0][3], b[2], b[3]);
                mma_bf16(acc[1][2*p+1], a[1][0], a[1][1], a[1][2], a[1][3], b[2], b[3]);
            }
        }
        __syncthreads();
        if (c + 2 < NCHUNK) load_stage(s, (c + 2) * 64);
        asm volatile("cp.async.commit_group;");
    }

    #pragma unroll
    for (int mt = 0; mt < 2; mt++) {
        int r = rowBlock + m0 + mt * 16 + l4;
        #pragma unroll
        for (int nt = 0; nt < NT; nt++) {
            int c = colBlock + n0 + nt * 8 + lm * 2;
            if (r < M)
                *(float2*)(C + (size_t)r * Nc + c) =
                    make_float2(acc[mt][nt][0], acc[mt][nt][1]);
            if (r + 8 < M)
                *(float2*)(C + (size_t)(r + 8) * Nc + c) =
                    make_float2(acc[mt][nt][2], acc[mt][nt][3]);
        }
    }
}

// ---------------------------------------------------------------------------
// CSR SPMM0 + fused relu(h+b1) + bf16 split -> writes g_A2 row ([Ah|Al]).
// ---------------------------------------------------------------------------
__global__ __launch_bounds__(256) void spmm0_csr(const float* __restrict__ b1)
{
    int r = blockIdx.x * 8 + (threadIdx.x >> 5);
    if (r >= N_NODES) return;
    const int lane = threadIdx.x & 31;
    const int beg = g_ptr0[r];
    const int end = g_ptr0[r + 1];

    float4 a0 = make_float4(0.f, 0.f, 0.f, 0.f);
    float4 a1 = a0;

    int e = beg;
    for (; e + 2 <= end; e += 2) {
        int2 ea = g_e0[e], eb = g_e0[e + 1];
        float va = __int_as_float(ea.y), vb = __int_as_float(eb.y);
        const float4* sa = (const float4*)(g_xw1 + (size_t)ea.x * NHID) + lane * 2;
        const float4* sb = (const float4*)(g_xw1 + (size_t)eb.x * NHID) + lane * 2;
        float4 xa0 = sa[0], xa1 = sa[1], xb0 = sb[0], xb1 = sb[1];
        a0.x += va * xa0.x; a0.y += va * xa0.y; a0.z += va * xa0.z; a0.w += va * xa0.w;
        a1.x += va * xa1.x; a1.y += va * xa1.y; a1.z += va * xa1.z; a1.w += va * xa1.w;
        a0.x += vb * xb0.x; a0.y += vb * xb0.y; a0.z += vb * xb0.z; a0.w += vb * xb0.w;
        a1.x += vb * xb1.x; a1.y += vb * xb1.y; a1.z += vb * xb1.z; a1.w += vb * xb1.w;
    }
    if (e < end) {
        int2 ea = g_e0[e];
        float va = __int_as_float(ea.y);
        const float4* sa = (const float4*)(g_xw1 + (size_t)ea.x * NHID) + lane * 2;
        float4 xa0 = sa[0], xa1 = sa[1];
        a0.x += va * xa0.x; a0.y += va * xa0.y; a0.z += va * xa0.z; a0.w += va * xa0.w;
        a1.x += va * xa1.x; a1.y += va * xa1.y; a1.z += va * xa1.z; a1.w += va * xa1.w;
    }

    const int f = lane * 8;
    float4 bb0 = *(const float4*)(b1 + f);
    float4 bb1 = *(const float4*)(b1 + f + 4);
    float h[8];
    h[0] = fmaxf(a0.x + bb0.x, 0.f); h[1] = fmaxf(a0.y + bb0.y, 0.f);
    h[2] = fmaxf(a0.z + bb0.z, 0.f); h[3] = fmaxf(a0.w + bb0.w, 0.f);
    h[4] = fmaxf(a1.x + bb1.x, 0.f); h[5] = fmaxf(a1.y + bb1.y, 0.f);
    h[6] = fmaxf(a1.z + bb1.z, 0.f); h[7] = fmaxf(a1.w + bb1.w, 0.f);

    unsigned long long ph[2] = {0ull, 0ull}, pl[2] = {0ull, 0ull};
    #pragma unroll
    for (int i = 0; i < 8; i++) {
        __nv_bfloat16 hi = __float2bfloat16(h[i]);
        __nv_bfloat16 lo = __float2bfloat16(h[i] - __bfloat162float(hi));
        ph[i >> 2] |= (unsigned long long)__bfloat16_as_ushort(hi) << (16 * (i & 3));
        pl[i >> 2] |= (unsigned long long)__bfloat16_as_ushort(lo) << (16 * (i & 3));
    }
    __nv_bfloat16* row = g_A2 + (size_t)r * (2 * NHID) + f;
    *(unsigned long long*)(row)            = ph[0];
    *(unsigned long long*)(row + 4)        = ph[1];
    *(unsigned long long*)(row + NHID)     = pl[0];
    *(unsigned long long*)(row + NHID + 4) = pl[1];
}

// ---------------------------------------------------------------------------
// CSR SPMM1: warp per row, lane handles 2 features. Writes g_h2 directly.
// ---------------------------------------------------------------------------
__global__ __launch_bounds__(256) void spmm1_csr()
{
    int r = blockIdx.x * 8 + (threadIdx.x >> 5);
    if (r >= N_NODES) return;
    const int lane = threadIdx.x & 31;
    const int beg = g_ptr1[r];
    const int end = g_ptr1[r + 1];

    float2 acc = make_float2(0.f, 0.f);
    int e = beg;
    for (; e + 2 <= end; e += 2) {
        int2 ea = g_e1[e], eb = g_e1[e + 1];
        float va = __int_as_float(ea.y), vb = __int_as_float(eb.y);
        float2 xa = ((const float2*)(g_hw2 + (size_t)ea.x * NCLASS))[lane];
        float2 xb = ((const float2*)(g_hw2 + (size_t)eb.x * NCLASS))[lane];
        acc.x += va * xa.x; acc.y += va * xa.y;
        acc.x += vb * xb.x; acc.y += vb * xb.y;
    }
    if (e < end) {
        int2 ea = g_e1[e];
        float va = __int_as_float(ea.y);
        float2 xa = ((const float2*)(g_hw2 + (size_t)ea.x * NCLASS))[lane];
        acc.x += va * xa.x; acc.y += va * xa.y;
    }
    ((float2*)(g_h2 + (size_t)r * NCLASS))[lane] = acc;
}

// ---------------------------------------------------------------------------
// Final: logits = (h2 + b2) @ LW + Lb ; log_softmax. One warp per node.
// ---------------------------------------------------------------------------
__global__ __launch_bounds__(256) void final_kernel(
    const float* __restrict__ b2, const float* __restrict__ LW,
    const float* __restrict__ Lb, float* __restrict__ out)
{
    __shared__ float sLW[NCLASS * NCLASS];
    __shared__ float sh2[8][NCLASS];
    const int tid = threadIdx.x;
    for (int i = tid; i < NCLASS * NCLASS; i += 256) sLW[i] = LW[i];

    const int warp = tid >> 5;
    const int lane = tid & 31;
    const int node = blockIdx.x * 8 + warp;

    if (node < N_NODES) {
        sh2[warp][lane]      = g_h2[(long)node * NCLASS + lane]      + b2[lane];
        sh2[warp][lane + 32] = g_h2[(long)node * NCLASS + lane + 32] + b2[lane + 32];
    }
    __syncthreads();
    if (node >= N_NODES) return;

    float l0 = Lb[lane];
    float l1 = Lb[lane + 32];
    #pragma unroll
    for (int k = 0; k < NCLASS; k++) {
        float hv = sh2[warp][k];
        l0 += hv * sLW[k * NCLASS + lane];
        l1 += hv * sLW[k * NCLASS + lane + 32];
    }

    float m = fmaxf(l0, l1);
    #pragma unroll
    for (int off = 16; off; off >>= 1)
        m = fmaxf(m, __shfl_xor_sync(0xffffffff, m, off));
    float s = expf(l0 - m) + expf(l1 - m);
    #pragma unroll
    for (int off = 16; off; off >>= 1)
        s += __shfl_xor_sync(0xffffffff, s, off);
    float lse = m + logf(s);

    out[(long)node * NCLASS + lane]      = l0 - lse;
    out[(long)node * NCLASS + lane + 32] = l1 - lse;
}

// ---------------------------------------------------------------------------
// Launch — side stream: W1 split, CSR build, W2 split. Serial tail on main.
// ---------------------------------------------------------------------------
extern "C" void kernel_launch(void* const* d_in, const int* in_sizes, int n_in,
                              void* d_out, int out_size)
{
    const float* x   = (const float*)d_in[0];
    const float* a0v = (const float*)d_in[1];
    const float* a1v = (const float*)d_in[2];
    const float* W1  = (const float*)d_in[3];
    const float* b1  = (const float*)d_in[4];
    const float* W2  = (const float*)d_in[5];
    const float* b2  = (const float*)d_in[6];
    const float* LW  = (const float*)d_in[7];
    const float* Lb  = (const float*)d_in[8];
    const int*   a0r = (const int*)d_in[9];
    const int*   a0c = (const int*)d_in[10];
    const int*   a1r = (const int*)d_in[11];
    const int*   a1c = (const int*)d_in[12];
    float* out = (float*)d_out;

    float *p_xw1, *p_hw2;
    __nv_bfloat16 *p_A1, *p_B1, *p_A2, *p_B2;
    cudaGetSymbolAddress((void**)&p_xw1, g_xw1);
    cudaGetSymbolAddress((void**)&p_hw2, g_hw2);
    cudaGetSymbolAddress((void**)&p_A1,  g_A1);
    cudaGetSymbolAddress((void**)&p_B1,  g_B1);
    cudaGetSymbolAddress((void**)&p_A2,  g_A2);
    cudaGetSymbolAddress((void**)&p_B2,  g_B2);

    const int SMEM1 = 2 * (128 * 72 + 128 * 72) * 2;  // 73728
    const int SMEM2 = 2 * (128 * 72 + 64 * 72) * 2;   // 55296
    cudaFuncSetAttribute(bf16_gemm<128>,
                         cudaFuncAttributeMaxDynamicSharedMemorySize, SMEM1);
    cudaFuncSetAttribute(bf16_gemm<64>,
                         cudaFuncAttributeMaxDynamicSharedMemorySize, SMEM2);

    // side stream + events (host objects; created during capture call only)
    cudaStream_t s2;
    cudaStreamCreateWithFlags(&s2, cudaStreamNonBlocking);
    cudaEvent_t evFork, evW1, evJoin;
    cudaEventCreateWithFlags(&evFork, cudaEventDisableTiming);
    cudaEventCreateWithFlags(&evW1,   cudaEventDisableTiming);
    cudaEventCreateWithFlags(&evJoin, cudaEventDisableTiming);

    // ---- fork ----
    cudaEventRecord(evFork, 0);
    cudaStreamWaitEvent(s2, evFork, 0);

    // ---- stream B: W1 split -> evW1 -> CSR build -> W2 split -> evJoin ----
    conv_w<<<(NFEAT * NHID + 255) / 256, 256, 0, s2>>>(W1, p_B1, NFEAT, NHID);
    cudaEventRecord(evW1, s2);
    csr_zero<<<(N_NODES + 255) / 256, 256, 0, s2>>>();
    csr_hist<<<(2 * E_EDGES + 255) / 256, 256, 0, s2>>>(a0r, a1r);
    csr_scan<<<2, 1024, 0, s2>>>();
    csr_scatter<<<(2 * E_EDGES + 255) / 256, 256, 0, s2>>>(a0r, a0c, a0v,
                                                           a1r, a1c, a1v);
    conv_w<<<(NHID * NCLASS + 255) / 256, 256, 0, s2>>>(W2, p_B2, NHID, NCLASS);
    cudaEventRecord(evJoin, s2);

    // ---- stream A (default): x split, GEMM1 ----
    {
        long total = (long)M_PAD * (NFEAT / 4);
        conv_split_x<<<(int)((total + 255) / 256), 256>>>(x, p_A1, N_NODES, NFEAT);
    }
    cudaStreamWaitEvent(0, evW1, 0);
    {
        dim3 grid(NHID / 128, M_PAD / 128);
        bf16_gemm<128><<<grid, 256, SMEM1>>>(p_A1, p_B1, p_xw1,
                                             N_NODES, NHID, 3 * NFEAT, 2 * NFEAT);
    }

    // ---- join CSR, then serial tail ----
    cudaStreamWaitEvent(0, evJoin, 0);

    // SPMM0 (CSR) + fused relu+b1+split -> g_A2
    spmm0_csr<<<(N_NODES + 7) / 8, 256>>>(b1);

    // GEMM2: g_hw2 = relu(h+b1) @ W2 (bf16 3-term, Kp = 768)
    {
        dim3 grid(1, M_PAD / 128);
        bf16_gemm<64><<<grid, 256, SMEM2>>>(p_A2, p_B2, p_hw2,
                                            N_NODES, NCLASS, 3 * NHID, 2 * NHID);
    }

    // SPMM1 (CSR) -> g_h2
    spmm1_csr<<<(N_NODES + 7) / 8, 256>>>();

    // Final linear + log_softmax
    final_kernel<<<(N_NODES + 7) / 8, 256>>>(b2, LW, Lb, out);
}

// round 16
// speedup vs baseline: 1.1563x; 1.1528x over previous
#include <cuda_runtime.h>
#include <cuda_bf16.h>
#include <math.h>
#include <stdint.h>

#define N_NODES 50000
#define M_PAD   50048          // 391 * 128
#define E_EDGES 800000
#define NFEAT   512
#define NHID    256
#define NCLASS  64

// fp32 scratch
__device__ float g_hw2[N_NODES * NCLASS]; // relu(h+b1) @ W2
__device__ float g_xw1[N_NODES * NHID];   // x @ W1 (fp32)

// bf16 split operands:  A' = [Ah | Al | Ah],  B't = [Bh | Bh | Bl] (n-major rows)
__device__ __nv_bfloat16 g_A1[(size_t)M_PAD * (3 * NFEAT)];
__device__ __nv_bfloat16 g_B1[(size_t)NHID  * (3 * NFEAT)];
__device__ __nv_bfloat16 g_A2[(size_t)M_PAD * (3 * NHID)];   // rows >= N_NODES stay 0
__device__ __nv_bfloat16 g_B2[(size_t)NCLASS * (3 * NHID)];

// CSR scratch (built on device every call)
__device__ int  g_cnt0[N_NODES];
__device__ int  g_cnt1[N_NODES];
__device__ int  g_ptr0[N_NODES + 1];
__device__ int  g_ptr1[N_NODES + 1];
__device__ int  g_slot0[E_EDGES];
__device__ int  g_slot1[E_EDGES];
__device__ int2 g_e0[E_EDGES];   // (col, val bits), grouped by row
__device__ int2 g_e1[E_EDGES];

// ---------------------------------------------------------------------------
// CSR build
// ---------------------------------------------------------------------------
__global__ void csr_zero() {
    int i = blockIdx.x * blockDim.x + threadIdx.x;
    if (i < N_NODES) { g_cnt0[i] = 0; g_cnt1[i] = 0; }
}

__global__ void csr_hist(const int* __restrict__ r0, const int* __restrict__ r1) {
    int i = blockIdx.x * blockDim.x + threadIdx.x;
    if (i < E_EDGES) {
        g_slot0[i] = atomicAdd(&g_cnt0[r0[i]], 1);
    } else if (i < 2 * E_EDGES) {
        int e = i - E_EDGES;
        g_slot1[e] = atomicAdd(&g_cnt1[r1[e]], 1);
    }
}

__global__ __launch_bounds__(1024) void csr_scan() {
    const int* cnt = blockIdx.x == 0 ? g_cnt0 : g_cnt1;
    int* ptr = blockIdx.x == 0 ? g_ptr0 : g_ptr1;
    __shared__ int tmp[1024];
    const int tid = threadIdx.x;
    const int chunk = (N_NODES + 1023) / 1024;   // 49
    int start = tid * chunk;
    int end   = start + chunk; if (end > N_NODES) end = N_NODES;
    int s = 0;
    for (int i = start; i < end; i++) s += cnt[i];
    tmp[tid] = s;
    __syncthreads();
    for (int d = 1; d < 1024; d <<= 1) {
        int t = (tid >= d) ? tmp[tid - d] : 0;
        __syncthreads();
        tmp[tid] += t;
        __syncthreads();
    }
    int off = tmp[tid] - s;
    for (int i = start; i < end; i++) {
        ptr[i] = off;
        off += cnt[i];
    }
    if (tid == 1023) ptr[N_NODES] = tmp[1023];
}

__global__ void csr_scatter(
    const int* __restrict__ r0, const int* __restrict__ c0, const float* __restrict__ v0,
    const int* __restrict__ r1, const int* __restrict__ c1, const float* __restrict__ v1)
{
    int i = blockIdx.x * blockDim.x + threadIdx.x;
    if (i < E_EDGES) {
        int p = g_ptr0[r0[i]] + g_slot0[i];
        g_e0[p] = make_int2(c0[i], __float_as_int(v0[i]));
    } else if (i < 2 * E_EDGES) {
        int e = i - E_EDGES;
        int p = g_ptr1[r1[e]] + g_slot1[e];
        g_e1[p] = make_int2(c1[e], __float_as_int(v1[e]));
    }
}

// ---------------------------------------------------------------------------
// Split fp32 matrix -> bf16 [Ah | Al | Ah]  (x input only)
// ---------------------------------------------------------------------------
__global__ __launch_bounds__(256) void conv_split_x(
    const float* __restrict__ src, __nv_bfloat16* __restrict__ dst,
    int Msrc, int K)
{
    long idx = (long)blockIdx.x * blockDim.x + threadIdx.x;
    long total = (long)M_PAD * (K / 4);
    if (idx >= total) return;
    int r  = (int)(idx / (K / 4));
    int k4 = (int)(idx % (K / 4)) * 4;

    float4 v = make_float4(0.f, 0.f, 0.f, 0.f);
    if (r < Msrc) v = *(const float4*)(src + (size_t)r * K + k4);
    float a[4] = {v.x, v.y, v.z, v.w};
    unsigned long long ph = 0, pl = 0;
    #pragma unroll
    for (int i = 0; i < 4; i++) {
        __nv_bfloat16 h = __float2bfloat16(a[i]);
        __nv_bfloat16 l = __float2bfloat16(a[i] - __bfloat162float(h));
        ph |= (unsigned long long)__bfloat16_as_ushort(h) << (16 * i);
        pl |= (unsigned long long)__bfloat16_as_ushort(l) << (16 * i);
    }
    __nv_bfloat16* row = dst + (size_t)r * 3 * K;
    *(unsigned long long*)(row + k4)         = ph;
    *(unsigned long long*)(row + K + k4)     = pl;
    *(unsigned long long*)(row + 2 * K + k4) = ph;
}

// ---------------------------------------------------------------------------
// Split weight W[K][N] (row-major) -> Bt[N][3K] bf16 = [Bh | Bh | Bl]
// ---------------------------------------------------------------------------
__global__ __launch_bounds__(256) void conv_w(
    const float* __restrict__ W, __nv_bfloat16* __restrict__ Bt, int K, int N)
{
    int idx = blockIdx.x * blockDim.x + threadIdx.x;
    if (idx >= K * N) return;
    int n = idx / K, k = idx % K;
    float w = W[(size_t)k * N + n];
    __nv_bfloat16 h = __float2bfloat16(w);
    __nv_bfloat16 l = __float2bfloat16(w - __bfloat162float(h));
    __nv_bfloat16* row = Bt + (size_t)n * 3 * K;
    row[k]         = h;
    row[K + k]     = h;
    row[2 * K + k] = l;
}

// ---------------------------------------------------------------------------
// bf16 tensor-core GEMM: C[M][Nc](fp32) = A[M_PAD][Kp] @ Bt[Nc][Kp]^T
// 128 x BTN block tile, 8 warps, K-step 64, 2-stage cp.async pipeline,
// ldmatrix.x4 loads, 2 CTAs/SM.  (R13-proven version)
// ---------------------------------------------------------------------------
__device__ __forceinline__ void cp16(uint32_t dst_smem, const void* src) {
    asm volatile("cp.async.cg.shared.global [%0], [%1], 16;"
                 :: "r"(dst_smem), "l"(src));
}

__device__ __forceinline__ void ldm_x4(uint32_t r[4], uint32_t addr) {
    asm volatile("ldmatrix.sync.aligned.m8n8.x4.shared.b16 {%0,%1,%2,%3}, [%4];"
                 : "=r"(r[0]), "=r"(r[1]), "=r"(r[2]), "=r"(r[3]) : "r"(addr));
}

__device__ __forceinline__ void mma_bf16(float c[4],
    uint32_t a0, uint32_t a1, uint32_t a2, uint32_t a3,
    uint32_t b0, uint32_t b1)
{
    asm volatile(
        "mma.sync.aligned.m16n8k16.row.col.f32.bf16.bf16.f32 "
        "{%0,%1,%2,%3}, {%4,%5,%6,%7}, {%8,%9}, {%0,%1,%2,%3};"
        : "+f"(c[0]), "+f"(c[1]), "+f"(c[2]), "+f"(c[3])
        : "r"(a0), "r"(a1), "r"(a2), "r"(a3), "r"(b0), "r"(b1));
}

template<int BTN>
__global__ __launch_bounds__(256, 2) void bf16_gemm(
    const __nv_bfloat16* __restrict__ A, const __nv_bfloat16* __restrict__ Bt,
    float* __restrict__ C, int M, int Nc, int Kp)
{
    constexpr int P = 72;                  // 144B pitch: ldmatrix conflict-free
    constexpr int ASTRIDE = 128 * P * 2;
    constexpr int BSTRIDE = BTN * P * 2;
    extern __shared__ __align__(16) char smem[];
    const uint32_t smemBase = (uint32_t)__cvta_generic_to_shared(smem);
    const uint32_t asBase = smemBase;
    const uint32_t bsBase = smemBase + 2 * ASTRIDE;

    const int tid  = threadIdx.x;
    const int warp = tid >> 5;
    const int lane = tid & 31;
    const int l4 = lane >> 2;
    const int lm = lane & 3;
    const int warpM = warp & 3;
    const int warpN = warp >> 2;
    constexpr int WN = BTN / 2;
    constexpr int NT = WN / 8;
    constexpr int NP = NT / 2;
    const int m0 = warpM * 32;
    const int n0 = warpN * WN;
    const int rowBlock = blockIdx.y * 128;
    const int colBlock = blockIdx.x * BTN;

    const int aRowL = ((lane >> 3) & 1) * 8 + (lane & 7);
    const int aColH = (lane >> 4) * 8;
    uint32_t aoff[2];
    #pragma unroll
    for (int mt = 0; mt < 2; mt++)
        aoff[mt] = ((m0 + mt * 16 + aRowL) * P + aColH) * 2;
    const int bColH = ((lane >> 3) & 1) * 8;
    uint32_t boff[NP > 0 ? NP : 1];
    #pragma unroll
    for (int p = 0; p < NP; p++)
        boff[p] = ((n0 + (2 * p + (lane >> 4)) * 8 + (lane & 7)) * P + bColH) * 2;

    float acc[2][NT][4];
    #pragma unroll
    for (int mt = 0; mt < 2; mt++)
        #pragma unroll
        for (int nt = 0; nt < NT; nt++)
            #pragma unroll
            for (int j = 0; j < 4; j++) acc[mt][nt][j] = 0.f;

    auto load_stage = [&](int s, int k0) {
        uint32_t aS = asBase + s * ASTRIDE;
        uint32_t bS = bsBase + s * BSTRIDE;
        #pragma unroll
        for (int ch = tid; ch < 1024; ch += 256) {         // A: 128 rows x 8 chunks
            int r = ch >> 3, c = ch & 7;
            cp16(aS + (r * P + c * 8) * 2,
                 A + (size_t)(rowBlock + r) * Kp + k0 + c * 8);
        }
        #pragma unroll
        for (int ch = tid; ch < BTN * 8; ch += 256) {      // B: BTN rows x 8 chunks
            int r = ch >> 3, c = ch & 7;
            cp16(bS + (r * P + c * 8) * 2,
                 Bt + (size_t)(colBlock + r) * Kp + k0 + c * 8);
        }
    };

    load_stage(0, 0);
    asm volatile("cp.async.commit_group;");
    load_stage(1, 64);
    asm volatile("cp.async.commit_group;");

    const int NCHUNK = Kp / 64;
    for (int c = 0; c < NCHUNK; c++) {
        int s = c & 1;
        asm volatile("cp.async.wait_group 1;");
        __syncthreads();

        const uint32_t aStage = asBase + s * ASTRIDE;
        const uint32_t bStage = bsBase + s * BSTRIDE;

        #pragma unroll
        for (int kk = 0; kk < 64; kk += 16) {
            uint32_t a[2][4];
            ldm_x4(a[0], aStage + aoff[0] + kk * 2);
            ldm_x4(a[1], aStage + aoff[1] + kk * 2);
            #pragma unroll
            for (int p = 0; p < NP; p++) {
                uint32_t b[4];
                ldm_x4(b, bStage + boff[p] + kk * 2);
                mma_bf16(acc[0][2*p],   a[0][0], a[0][1], a[0][2], a[0][3], b[0], b[1]);
                mma_bf16(acc[1][2*p],   a[1][0], a[1][1], a[1][2], a[1][3], b[0], b[1]);
                mma_bf16(acc[0][2*p+1], a[0][0], a[0][1], a[0][2], a[0][3], b[2], b[3]);
                mma_bf16(acc[1][2*p+1], a[1][0], a[1][1], a[1][2], a[1][3], b[2], b[3]);
            }
        }
        __syncthreads();
        if (c + 2 < NCHUNK) load_stage(s, (c + 2) * 64);
        asm volatile("cp.async.commit_group;");
    }

    #pragma unroll
    for (int mt = 0; mt < 2; mt++) {
        int r = rowBlock + m0 + mt * 16 + l4;
        #pragma unroll
        for (int nt = 0; nt < NT; nt++) {
            int c = colBlock + n0 + nt * 8 + lm * 2;
            if (r < M)
                *(float2*)(C + (size_t)r * Nc + c) =
                    make_float2(acc[mt][nt][0], acc[mt][nt][1]);
            if (r + 8 < M)
                *(float2*)(C + (size_t)(r + 8) * Nc + c) =
                    make_float2(acc[mt][nt][2], acc[mt][nt][3]);
        }
    }
}

// ---------------------------------------------------------------------------
// CSR SPMM0 + fused relu(h+b1) + bf16 split -> writes g_A2 row ([Ah|Al|Ah]).
// ---------------------------------------------------------------------------
__global__ __launch_bounds__(256) void spmm0_csr(const float* __restrict__ b1)
{
    int r = blockIdx.x * 8 + (threadIdx.x >> 5);
    if (r >= N_NODES) return;
    const int lane = threadIdx.x & 31;
    const int beg = g_ptr0[r];
    const int end = g_ptr0[r + 1];

    float4 a0 = make_float4(0.f, 0.f, 0.f, 0.f);
    float4 a1 = a0;

    int e = beg;
    for (; e + 2 <= end; e += 2) {
        int2 ea = g_e0[e], eb = g_e0[e + 1];
        float va = __int_as_float(ea.y), vb = __int_as_float(eb.y);
        const float4* sa = (const float4*)(g_xw1 + (size_t)ea.x * NHID) + lane * 2;
        const float4* sb = (const float4*)(g_xw1 + (size_t)eb.x * NHID) + lane * 2;
        float4 xa0 = sa[0], xa1 = sa[1], xb0 = sb[0], xb1 = sb[1];
        a0.x += va * xa0.x; a0.y += va * xa0.y; a0.z += va * xa0.z; a0.w += va * xa0.w;
        a1.x += va * xa1.x; a1.y += va * xa1.y; a1.z += va * xa1.z; a1.w += va * xa1.w;
        a0.x += vb * xb0.x; a0.y += vb * xb0.y; a0.z += vb * xb0.z; a0.w += vb * xb0.w;
        a1.x += vb * xb1.x; a1.y += vb * xb1.y; a1.z += vb * xb1.z; a1.w += vb * xb1.w;
    }
    if (e < end) {
        int2 ea = g_e0[e];
        float va = __int_as_float(ea.y);
        const float4* sa = (const float4*)(g_xw1 + (size_t)ea.x * NHID) + lane * 2;
        float4 xa0 = sa[0], xa1 = sa[1];
        a0.x += va * xa0.x; a0.y += va * xa0.y; a0.z += va * xa0.z; a0.w += va * xa0.w;
        a1.x += va * xa1.x; a1.y += va * xa1.y; a1.z += va * xa1.z; a1.w += va * xa1.w;
    }

    const int f = lane * 8;
    float4 bb0 = *(const float4*)(b1 + f);
    float4 bb1 = *(const float4*)(b1 + f + 4);
    float h[8];
    h[0] = fmaxf(a0.x + bb0.x, 0.f); h[1] = fmaxf(a0.y + bb0.y, 0.f);
    h[2] = fmaxf(a0.z + bb0.z, 0.f); h[3] = fmaxf(a0.w + bb0.w, 0.f);
    h[4] = fmaxf(a1.x + bb1.x, 0.f); h[5] = fmaxf(a1.y + bb1.y, 0.f);
    h[6] = fmaxf(a1.z + bb1.z, 0.f); h[7] = fmaxf(a1.w + bb1.w, 0.f);

    unsigned long long ph[2] = {0ull, 0ull}, pl[2] = {0ull, 0ull};
    #pragma unroll
    for (int i = 0; i < 8; i++) {
        __nv_bfloat16 hi = __float2bfloat16(h[i]);
        __nv_bfloat16 lo = __float2bfloat16(h[i] - __bfloat162float(hi));
        ph[i >> 2] |= (unsigned long long)__bfloat16_as_ushort(hi) << (16 * (i & 3));
        pl[i >> 2] |= (unsigned long long)__bfloat16_as_ushort(lo) << (16 * (i & 3));
    }
    __nv_bfloat16* row = g_A2 + (size_t)r * (3 * NHID) + f;
    *(unsigned long long*)(row)                = ph[0];
    *(unsigned long long*)(row + 4)            = ph[1];
    *(unsigned long long*)(row + NHID)         = pl[0];
    *(unsigned long long*)(row + NHID + 4)     = pl[1];
    *(unsigned long long*)(row + 2 * NHID)     = ph[0];
    *(unsigned long long*)(row + 2 * NHID + 4) = ph[1];
}

// ---------------------------------------------------------------------------
// FUSED: CSR SPMM1 + (h2+b2)@LW+Lb + log_softmax -> out. Warp per row.
// ---------------------------------------------------------------------------
__global__ __launch_bounds__(256) void spmm1_final(
    const float* __restrict__ b2, const float* __restrict__ LW,
    const float* __restrict__ Lb, float* __restrict__ out)
{
    __shared__ float sLW[NCLASS * NCLASS];   // [k][c], 16KB
    __shared__ float sh2[8][NCLASS];
    const int tid = threadIdx.x;
    for (int i = tid; i < NCLASS * NCLASS; i += 256) sLW[i] = LW[i];
    __syncthreads();

    const int warp = tid >> 5;
    const int lane = tid & 31;
    const int r = blockIdx.x * 8 + warp;
    const bool valid = (r < N_NODES);

    if (valid) {
        const int beg = g_ptr1[r];
        const int end = g_ptr1[r + 1];
        float2 acc = make_float2(0.f, 0.f);
        int e = beg;
        for (; e + 2 <= end; e += 2) {
            int2 ea = g_e1[e], eb = g_e1[e + 1];
            float va = __int_as_float(ea.y), vb = __int_as_float(eb.y);
            float2 xa = ((const float2*)(g_hw2 + (size_t)ea.x * NCLASS))[lane];
            float2 xb = ((const float2*)(g_hw2 + (size_t)eb.x * NCLASS))[lane];
            acc.x += va * xa.x; acc.y += va * xa.y;
            acc.x += vb * xb.x; acc.y += vb * xb.y;
        }
        if (e < end) {
            int2 ea = g_e1[e];
            float va = __int_as_float(ea.y);
            float2 xa = ((const float2*)(g_hw2 + (size_t)ea.x * NCLASS))[lane];
            acc.x += va * xa.x; acc.y += va * xa.y;
        }
        // stage h2 row (+b2) into shared, same layout as the old final_kernel
        sh2[warp][2 * lane]     = acc.x + b2[2 * lane];
        sh2[warp][2 * lane + 1] = acc.y + b2[2 * lane + 1];
    }
    __syncwarp();
    if (!valid) return;

    float l0 = Lb[lane];
    float l1 = Lb[lane + 32];
    #pragma unroll
    for (int k = 0; k < NCLASS; k++) {
        float hv = sh2[warp][k];
        l0 += hv * sLW[k * NCLASS + lane];
        l1 += hv * sLW[k * NCLASS + lane + 32];
    }

    float m = fmaxf(l0, l1);
    #pragma unroll
    for (int off = 16; off; off >>= 1)
        m = fmaxf(m, __shfl_xor_sync(0xffffffff, m, off));
    float s = expf(l0 - m) + expf(l1 - m);
    #pragma unroll
    for (int off = 16; off; off >>= 1)
        s += __shfl_xor_sync(0xffffffff, s, off);
    float lse = m + logf(s);

    out[(size_t)r * NCLASS + lane]      = l0 - lse;
    out[(size_t)r * NCLASS + lane + 32] = l1 - lse;
}

// ---------------------------------------------------------------------------
// Launch — side stream: CSR build + W2 split (R13 schedule). Serial tail.
// ---------------------------------------------------------------------------
extern "C" void kernel_launch(void* const* d_in, const int* in_sizes, int n_in,
                              void* d_out, int out_size)
{
    const float* x   = (const float*)d_in[0];
    const float* a0v = (const float*)d_in[1];
    const float* a1v = (const float*)d_in[2];
    const float* W1  = (const float*)d_in[3];
    const float* b1  = (const float*)d_in[4];
    const float* W2  = (const float*)d_in[5];
    const float* b2  = (const float*)d_in[6];
    const float* LW  = (const float*)d_in[7];
    const float* Lb  = (const float*)d_in[8];
    const int*   a0r = (const int*)d_in[9];
    const int*   a0c = (const int*)d_in[10];
    const int*   a1r = (const int*)d_in[11];
    const int*   a1c = (const int*)d_in[12];
    float* out = (float*)d_out;

    float *p_xw1, *p_hw2;
    __nv_bfloat16 *p_A1, *p_B1, *p_A2, *p_B2;
    cudaGetSymbolAddress((void**)&p_xw1, g_xw1);
    cudaGetSymbolAddress((void**)&p_hw2, g_hw2);
    cudaGetSymbolAddress((void**)&p_A1,  g_A1);
    cudaGetSymbolAddress((void**)&p_B1,  g_B1);
    cudaGetSymbolAddress((void**)&p_A2,  g_A2);
    cudaGetSymbolAddress((void**)&p_B2,  g_B2);

    const int SMEM1 = 2 * (128 * 72 + 128 * 72) * 2;  // 73728
    const int SMEM2 = 2 * (128 * 72 + 64 * 72) * 2;   // 55296
    cudaFuncSetAttribute(bf16_gemm<128>,
                         cudaFuncAttributeMaxDynamicSharedMemorySize, SMEM1);
    cudaFuncSetAttribute(bf16_gemm<64>,
                         cudaFuncAttributeMaxDynamicSharedMemorySize, SMEM2);

    // side stream + events (host objects; created during capture call only)
    cudaStream_t s2;
    cudaStreamCreateWithFlags(&s2, cudaStreamNonBlocking);
    cudaEvent_t evFork, evJoin;
    cudaEventCreateWithFlags(&evFork, cudaEventDisableTiming);
    cudaEventCreateWithFlags(&evJoin, cudaEventDisableTiming);

    // ---- fork ----
    cudaEventRecord(evFork, 0);
    cudaStreamWaitEvent(s2, evFork, 0);

    // ---- stream B: CSR build (both adjacencies) + W2 split ----
    csr_zero<<<(N_NODES + 255) / 256, 256, 0, s2>>>();
    csr_hist<<<(2 * E_EDGES + 255) / 256, 256, 0, s2>>>(a0r, a1r);
    csr_scan<<<2, 1024, 0, s2>>>();
    csr_scatter<<<(2 * E_EDGES + 255) / 256, 256, 0, s2>>>(a0r, a0c, a0v,
                                                           a1r, a1c, a1v);
    conv_w<<<(NHID * NCLASS + 255) / 256, 256, 0, s2>>>(W2, p_B2, NHID, NCLASS);
    cudaEventRecord(evJoin, s2);

    // ---- stream A (default): x split, W1 split, GEMM1 ----
    {
        long total = (long)M_PAD * (NFEAT / 4);
        conv_split_x<<<(int)((total + 255) / 256), 256>>>(x, p_A1, N_NODES, NFEAT);
        conv_w<<<(NFEAT * NHID + 255) / 256, 256>>>(W1, p_B1, NFEAT, NHID);
    }
    {
        dim3 grid(NHID / 128, M_PAD / 128);
        bf16_gemm<128><<<grid, 256, SMEM1>>>(p_A1, p_B1, p_xw1,
                                             N_NODES, NHID, 3 * NFEAT);
    }

    // ---- join CSR, then serial tail ----
    cudaStreamWaitEvent(0, evJoin, 0);

    // SPMM0 (CSR) + fused relu+b1+split -> g_A2
    spmm0_csr<<<(N_NODES + 7) / 8, 256>>>(b1);

    // GEMM2: g_hw2 = relu(h+b1) @ W2 (bf16 3-term, Kp = 768)
    {
        dim3 grid(1, M_PAD / 128);
        bf16_gemm<64><<<grid, 256, SMEM2>>>(p_A2, p_B2, p_hw2,
                                            N_NODES, NCLASS, 3 * NHID);
    }

    // FUSED SPMM1 + final linear + log_softmax
    spmm1_final<<<(N_NODES + 7) / 8, 256>>>(b2, LW, Lb, out);
}

// round 17
// speedup vs baseline: 1.1762x; 1.0172x over previous
#include <cuda_runtime.h>
#include <cuda_bf16.h>
#include <math.h>
#include <stdint.h>

#define N_NODES 50000
#define M_PAD   50048          // 391 * 128
#define E_EDGES 800000
#define NFEAT   512
#define NHID    256
#define NCLASS  64

// fp32 scratch
__device__ float g_hw2[N_NODES * NCLASS]; // relu(h+b1) @ W2
__device__ float g_xw1[N_NODES * NHID];   // x @ W1 (fp32)

// bf16 split operands:  A' = [Ah | Al | Ah],  B't = [Bh | Bh | Bl] (n-major rows)
__device__ __nv_bfloat16 g_A1[(size_t)M_PAD * (3 * NFEAT)];
__device__ __nv_bfloat16 g_B1[(size_t)NHID  * (3 * NFEAT)];
__device__ __nv_bfloat16 g_A2[(size_t)M_PAD * (3 * NHID)];   // rows >= N_NODES stay 0
__device__ __nv_bfloat16 g_B2[(size_t)NCLASS * (3 * NHID)];

// CSR scratch (built on device every call)
__device__ int  g_cnt0[N_NODES];
__device__ int  g_cnt1[N_NODES];
__device__ int  g_ptr0[N_NODES + 1];
__device__ int  g_ptr1[N_NODES + 1];
__device__ int  g_slot0[E_EDGES];
__device__ int  g_slot1[E_EDGES];
__device__ int2 g_e0[E_EDGES];   // (col, val bits), grouped by row
__device__ int2 g_e1[E_EDGES];

// ---------------------------------------------------------------------------
// CSR build
// ---------------------------------------------------------------------------
__global__ void csr_zero() {
    int i = blockIdx.x * blockDim.x + threadIdx.x;
    if (i < N_NODES) { g_cnt0[i] = 0; g_cnt1[i] = 0; }
}

__global__ void csr_hist(const int* __restrict__ r0, const int* __restrict__ r1) {
    int i = blockIdx.x * blockDim.x + threadIdx.x;
    if (i < E_EDGES) {
        g_slot0[i] = atomicAdd(&g_cnt0[r0[i]], 1);
    } else if (i < 2 * E_EDGES) {
        int e = i - E_EDGES;
        g_slot1[e] = atomicAdd(&g_cnt1[r1[e]], 1);
    }
}

__global__ __launch_bounds__(1024) void csr_scan() {
    const int* cnt = blockIdx.x == 0 ? g_cnt0 : g_cnt1;
    int* ptr = blockIdx.x == 0 ? g_ptr0 : g_ptr1;
    __shared__ int tmp[1024];
    const int tid = threadIdx.x;
    const int chunk = (N_NODES + 1023) / 1024;   // 49
    int start = tid * chunk;
    int end   = start + chunk; if (end > N_NODES) end = N_NODES;
    int s = 0;
    for (int i = start; i < end; i++) s += cnt[i];
    tmp[tid] = s;
    __syncthreads();
    for (int d = 1; d < 1024; d <<= 1) {
        int t = (tid >= d) ? tmp[tid - d] : 0;
        __syncthreads();
        tmp[tid] += t;
        __syncthreads();
    }
    int off = tmp[tid] - s;
    for (int i = start; i < end; i++) {
        ptr[i] = off;
        off += cnt[i];
    }
    if (tid == 1023) ptr[N_NODES] = tmp[1023];
}

__global__ void csr_scatter(
    const int* __restrict__ r0, const int* __restrict__ c0, const float* __restrict__ v0,
    const int* __restrict__ r1, const int* __restrict__ c1, const float* __restrict__ v1)
{
    int i = blockIdx.x * blockDim.x + threadIdx.x;
    if (i < E_EDGES) {
        int p = g_ptr0[r0[i]] + g_slot0[i];
        g_e0[p] = make_int2(c0[i], __float_as_int(v0[i]));
    } else if (i < 2 * E_EDGES) {
        int e = i - E_EDGES;
        int p = g_ptr1[r1[e]] + g_slot1[e];
        g_e1[p] = make_int2(c1[e], __float_as_int(v1[e]));
    }
}

// ---------------------------------------------------------------------------
// Split fp32 matrix -> bf16 [Ah | Al | Ah]  (x input only)
// ---------------------------------------------------------------------------
__global__ __launch_bounds__(256) void conv_split_x(
    const float* __restrict__ src, __nv_bfloat16* __restrict__ dst,
    int Msrc, int K)
{
    long idx = (long)blockIdx.x * blockDim.x + threadIdx.x;
    long total = (long)M_PAD * (K / 4);
    if (idx >= total) return;
    int r  = (int)(idx / (K / 4));
    int k4 = (int)(idx % (K / 4)) * 4;

    float4 v = make_float4(0.f, 0.f, 0.f, 0.f);
    if (r < Msrc) v = *(const float4*)(src + (size_t)r * K + k4);
    float a[4] = {v.x, v.y, v.z, v.w};
    unsigned long long ph = 0, pl = 0;
    #pragma unroll
    for (int i = 0; i < 4; i++) {
        __nv_bfloat16 h = __float2bfloat16(a[i]);
        __nv_bfloat16 l = __float2bfloat16(a[i] - __bfloat162float(h));
        ph |= (unsigned long long)__bfloat16_as_ushort(h) << (16 * i);
        pl |= (unsigned long long)__bfloat16_as_ushort(l) << (16 * i);
    }
    __nv_bfloat16* row = dst + (size_t)r * 3 * K;
    *(unsigned long long*)(row + k4)         = ph;
    *(unsigned long long*)(row + K + k4)     = pl;
    *(unsigned long long*)(row + 2 * K + k4) = ph;
}

// ---------------------------------------------------------------------------
// Split weight W[K][N] (row-major) -> Bt[N][3K] bf16 = [Bh | Bh | Bl]
// ---------------------------------------------------------------------------
__global__ __launch_bounds__(256) void conv_w(
    const float* __restrict__ W, __nv_bfloat16* __restrict__ Bt, int K, int N)
{
    int idx = blockIdx.x * blockDim.x + threadIdx.x;
    if (idx >= K * N) return;
    int n = idx / K, k = idx % K;
    float w = W[(size_t)k * N + n];
    __nv_bfloat16 h = __float2bfloat16(w);
    __nv_bfloat16 l = __float2bfloat16(w - __bfloat162float(h));
    __nv_bfloat16* row = Bt + (size_t)n * 3 * K;
    row[k]         = h;
    row[K + k]     = h;
    row[2 * K + k] = l;
}

// ---------------------------------------------------------------------------
// bf16 tensor-core GEMM: C[M][Nc](fp32) = A[M_PAD][Kp] @ Bt[Nc][Kp]^T
// 128 x BTN block tile, 8 warps, K-step 64, 2-stage cp.async pipeline,
// ldmatrix.x4 loads, 2 CTAs/SM.  colBase: N-block offset (for half launches).
// ---------------------------------------------------------------------------
__device__ __forceinline__ void cp16(uint32_t dst_smem, const void* src) {
    asm volatile("cp.async.cg.shared.global [%0], [%1], 16;"
                 :: "r"(dst_smem), "l"(src));
}

__device__ __forceinline__ void ldm_x4(uint32_t r[4], uint32_t addr) {
    asm volatile("ldmatrix.sync.aligned.m8n8.x4.shared.b16 {%0,%1,%2,%3}, [%4];"
                 : "=r"(r[0]), "=r"(r[1]), "=r"(r[2]), "=r"(r[3]) : "r"(addr));
}

__device__ __forceinline__ void mma_bf16(float c[4],
    uint32_t a0, uint32_t a1, uint32_t a2, uint32_t a3,
    uint32_t b0, uint32_t b1)
{
    asm volatile(
        "mma.sync.aligned.m16n8k16.row.col.f32.bf16.bf16.f32 "
        "{%0,%1,%2,%3}, {%4,%5,%6,%7}, {%8,%9}, {%0,%1,%2,%3};"
        : "+f"(c[0]), "+f"(c[1]), "+f"(c[2]), "+f"(c[3])
        : "r"(a0), "r"(a1), "r"(a2), "r"(a3), "r"(b0), "r"(b1));
}

template<int BTN>
__global__ __launch_bounds__(256, 2) void bf16_gemm(
    const __nv_bfloat16* __restrict__ A, const __nv_bfloat16* __restrict__ Bt,
    float* __restrict__ C, int M, int Nc, int Kp, int colBase)
{
    constexpr int P = 72;                  // 144B pitch: ldmatrix conflict-free
    constexpr int ASTRIDE = 128 * P * 2;
    constexpr int BSTRIDE = BTN * P * 2;
    extern __shared__ __align__(16) char smem[];
    const uint32_t smemBase = (uint32_t)__cvta_generic_to_shared(smem);
    const uint32_t asBase = smemBase;
    const uint32_t bsBase = smemBase + 2 * ASTRIDE;

    const int tid  = threadIdx.x;
    const int warp = tid >> 5;
    const int lane = tid & 31;
    const int l4 = lane >> 2;
    const int lm = lane & 3;
    const int warpM = warp & 3;
    const int warpN = warp >> 2;
    constexpr int WN = BTN / 2;
    constexpr int NT = WN / 8;
    constexpr int NP = NT / 2;
    const int m0 = warpM * 32;
    const int n0 = warpN * WN;
    const int rowBlock = blockIdx.y * 128;
    const int colBlock = (colBase + blockIdx.x) * BTN;

    const int aRowL = ((lane >> 3) & 1) * 8 + (lane & 7);
    const int aColH = (lane >> 4) * 8;
    uint32_t aoff[2];
    #pragma unroll
    for (int mt = 0; mt < 2; mt++)
        aoff[mt] = ((m0 + mt * 16 + aRowL) * P + aColH) * 2;
    const int bColH = ((lane >> 3) & 1) * 8;
    uint32_t boff[NP > 0 ? NP : 1];
    #pragma unroll
    for (int p = 0; p < NP; p++)
        boff[p] = ((n0 + (2 * p + (lane >> 4)) * 8 + (lane & 7)) * P + bColH) * 2;

    float acc[2][NT][4];
    #pragma unroll
    for (int mt = 0; mt < 2; mt++)
        #pragma unroll
        for (int nt = 0; nt < NT; nt++)
            #pragma unroll
            for (int j = 0; j < 4; j++) acc[mt][nt][j] = 0.f;

    auto load_stage = [&](int s, int k0) {
        uint32_t aS = asBase + s * ASTRIDE;
        uint32_t bS = bsBase + s * BSTRIDE;
        #pragma unroll
        for (int ch = tid; ch < 1024; ch += 256) {         // A: 128 rows x 8 chunks
            int r = ch >> 3, c = ch & 7;
            cp16(aS + (r * P + c * 8) * 2,
                 A + (size_t)(rowBlock + r) * Kp + k0 + c * 8);
        }
        #pragma unroll
        for (int ch = tid; ch < BTN * 8; ch += 256) {      // B: BTN rows x 8 chunks
            int r = ch >> 3, c = ch & 7;
            cp16(bS + (r * P + c * 8) * 2,
                 Bt + (size_t)(colBlock + r) * Kp + k0 + c * 8);
        }
    };

    load_stage(0, 0);
    asm volatile("cp.async.commit_group;");
    load_stage(1, 64);
    asm volatile("cp.async.commit_group;");

    const int NCHUNK = Kp / 64;
    for (int c = 0; c < NCHUNK; c++) {
        int s = c & 1;
        asm volatile("cp.async.wait_group 1;");
        __syncthreads();

        const uint32_t aStage = asBase + s * ASTRIDE;
        const uint32_t bStage = bsBase + s * BSTRIDE;

        #pragma unroll
        for (int kk = 0; kk < 64; kk += 16) {
            uint32_t a[2][4];
            ldm_x4(a[0], aStage + aoff[0] + kk * 2);
            ldm_x4(a[1], aStage + aoff[1] + kk * 2);
            #pragma unroll
            for (int p = 0; p < NP; p++) {
                uint32_t b[4];
                ldm_x4(b, bStage + boff[p] + kk * 2);
                mma_bf16(acc[0][2*p],   a[0][0], a[0][1], a[0][2], a[0][3], b[0], b[1]);
                mma_bf16(acc[1][2*p],   a[1][0], a[1][1], a[1][2], a[1][3], b[0], b[1]);
                mma_bf16(acc[0][2*p+1], a[0][0], a[0][1], a[0][2], a[0][3], b[2], b[3]);
                mma_bf16(acc[1][2*p+1], a[1][0], a[1][1], a[1][2], a[1][3], b[2], b[3]);
            }
        }
        __syncthreads();
        if (c + 2 < NCHUNK) load_stage(s, (c + 2) * 64);
        asm volatile("cp.async.commit_group;");
    }

    #pragma unroll
    for (int mt = 0; mt < 2; mt++) {
        int r = rowBlock + m0 + mt * 16 + l4;
        #pragma unroll
        for (int nt = 0; nt < NT; nt++) {
            int c = colBlock + n0 + nt * 8 + lm * 2;
            if (r < M)
                *(float2*)(C + (size_t)r * Nc + c) =
                    make_float2(acc[mt][nt][0], acc[mt][nt][1]);
            if (r + 8 < M)
                *(float2*)(C + (size_t)(r + 8) * Nc + c) =
                    make_float2(acc[mt][nt][2], acc[mt][nt][3]);
        }
    }
}

// ---------------------------------------------------------------------------
// CSR SPMM0 half (features [FOFF, FOFF+128)) + fused relu(h+b1) + bf16 split
// -> writes g_A2 row segment. Warp per row, lane = 4 features (float4).
// Per-feature accumulation order identical to the full version.
// ---------------------------------------------------------------------------
template<int FOFF>
__global__ __launch_bounds__(256) void spmm0_csr_half(const float* __restrict__ b1)
{
    int r = blockIdx.x * 8 + (threadIdx.x >> 5);
    if (r >= N_NODES) return;
    const int lane = threadIdx.x & 31;
    const int beg = g_ptr0[r];
    const int end = g_ptr0[r + 1];

    float4 a0 = make_float4(0.f, 0.f, 0.f, 0.f);

    int e = beg;
    for (; e + 2 <= end; e += 2) {
        int2 ea = g_e0[e], eb = g_e0[e + 1];
        float va = __int_as_float(ea.y), vb = __int_as_float(eb.y);
        float4 xa = *((const float4*)(g_xw1 + (size_t)ea.x * NHID + FOFF) + lane);
        float4 xb = *((const float4*)(g_xw1 + (size_t)eb.x * NHID + FOFF) + lane);
        a0.x += va * xa.x; a0.y += va * xa.y; a0.z += va * xa.z; a0.w += va * xa.w;
        a0.x += vb * xb.x; a0.y += vb * xb.y; a0.z += vb * xb.z; a0.w += vb * xb.w;
    }
    if (e < end) {
        int2 ea = g_e0[e];
        float va = __int_as_float(ea.y);
        float4 xa = *((const float4*)(g_xw1 + (size_t)ea.x * NHID + FOFF) + lane);
        a0.x += va * xa.x; a0.y += va * xa.y; a0.z += va * xa.z; a0.w += va * xa.w;
    }

    const int f = FOFF + lane * 4;
    float4 bb = *(const float4*)(b1 + f);
    float h[4];
    h[0] = fmaxf(a0.x + bb.x, 0.f);
    h[1] = fmaxf(a0.y + bb.y, 0.f);
    h[2] = fmaxf(a0.z + bb.z, 0.f);
    h[3] = fmaxf(a0.w + bb.w, 0.f);

    unsigned long long ph = 0ull, pl = 0ull;
    #pragma unroll
    for (int i = 0; i < 4; i++) {
        __nv_bfloat16 hi = __float2bfloat16(h[i]);
        __nv_bfloat16 lo = __float2bfloat16(h[i] - __bfloat162float(hi));
        ph |= (unsigned long long)__bfloat16_as_ushort(hi) << (16 * i);
        pl |= (unsigned long long)__bfloat16_as_ushort(lo) << (16 * i);
    }
    __nv_bfloat16* row = g_A2 + (size_t)r * (3 * NHID) + f;
    *(unsigned long long*)(row)            = ph;
    *(unsigned long long*)(row + NHID)     = pl;
    *(unsigned long long*)(row + 2 * NHID) = ph;
}

// ---------------------------------------------------------------------------
// FUSED: CSR SPMM1 + (h2+b2)@LW+Lb + log_softmax -> out. Warp per row.
// ---------------------------------------------------------------------------
__global__ __launch_bounds__(256) void spmm1_final(
    const float* __restrict__ b2, const float* __restrict__ LW,
    const float* __restrict__ Lb, float* __restrict__ out)
{
    __shared__ float sLW[NCLASS * NCLASS];   // [k][c], 16KB
    __shared__ float sh2[8][NCLASS];
    const int tid = threadIdx.x;
    for (int i = tid; i < NCLASS * NCLASS; i += 256) sLW[i] = LW[i];
    __syncthreads();

    const int warp = tid >> 5;
    const int lane = tid & 31;
    const int r = blockIdx.x * 8 + warp;
    const bool valid = (r < N_NODES);

    if (valid) {
        const int beg = g_ptr1[r];
        const int end = g_ptr1[r + 1];
        float2 acc = make_float2(0.f, 0.f);
        int e = beg;
        for (; e + 2 <= end; e += 2) {
            int2 ea = g_e1[e], eb = g_e1[e + 1];
            float va = __int_as_float(ea.y), vb = __int_as_float(eb.y);
            float2 xa = ((const float2*)(g_hw2 + (size_t)ea.x * NCLASS))[lane];
            float2 xb = ((const float2*)(g_hw2 + (size_t)eb.x * NCLASS))[lane];
            acc.x += va * xa.x; acc.y += va * xa.y;
            acc.x += vb * xb.x; acc.y += vb * xb.y;
        }
        if (e < end) {
            int2 ea = g_e1[e];
            float va = __int_as_float(ea.y);
            float2 xa = ((const float2*)(g_hw2 + (size_t)ea.x * NCLASS))[lane];
            acc.x += va * xa.x; acc.y += va * xa.y;
        }
        sh2[warp][2 * lane]     = acc.x + b2[2 * lane];
        sh2[warp][2 * lane + 1] = acc.y + b2[2 * lane + 1];
    }
    __syncwarp();
    if (!valid) return;

    float l0 = Lb[lane];
    float l1 = Lb[lane + 32];
    #pragma unroll
    for (int k = 0; k < NCLASS; k++) {
        float hv = sh2[warp][k];
        l0 += hv * sLW[k * NCLASS + lane];
        l1 += hv * sLW[k * NCLASS + lane + 32];
    }

    float m = fmaxf(l0, l1);
    #pragma unroll
    for (int off = 16; off; off >>= 1)
        m = fmaxf(m, __shfl_xor_sync(0xffffffff, m, off));
    float s = expf(l0 - m) + expf(l1 - m);
    #pragma unroll
    for (int off = 16; off; off >>= 1)
        s += __shfl_xor_sync(0xffffffff, s, off);
    float lse = m + logf(s);

    out[(size_t)r * NCLASS + lane]      = l0 - lse;
    out[(size_t)r * NCLASS + lane + 32] = l1 - lse;
}

// ---------------------------------------------------------------------------
// Launch — GEMM1 split by N-half; spmm0 half0 overlaps GEMM1 half1 on s2.
// ---------------------------------------------------------------------------
extern "C" void kernel_launch(void* const* d_in, const int* in_sizes, int n_in,
                              void* d_out, int out_size)
{
    const float* x   = (const float*)d_in[0];
    const float* a0v = (const float*)d_in[1];
    const float* a1v = (const float*)d_in[2];
    const float* W1  = (const float*)d_in[3];
    const float* b1  = (const float*)d_in[4];
    const float* W2  = (const float*)d_in[5];
    const float* b2  = (const float*)d_in[6];
    const float* LW  = (const float*)d_in[7];
    const float* Lb  = (const float*)d_in[8];
    const int*   a0r = (const int*)d_in[9];
    const int*   a0c = (const int*)d_in[10];
    const int*   a1r = (const int*)d_in[11];
    const int*   a1c = (const int*)d_in[12];
    float* out = (float*)d_out;

    float *p_xw1, *p_hw2;
    __nv_bfloat16 *p_A1, *p_B1, *p_A2, *p_B2;
    cudaGetSymbolAddress((void**)&p_xw1, g_xw1);
    cudaGetSymbolAddress((void**)&p_hw2, g_hw2);
    cudaGetSymbolAddress((void**)&p_A1,  g_A1);
    cudaGetSymbolAddress((void**)&p_B1,  g_B1);
    cudaGetSymbolAddress((void**)&p_A2,  g_A2);
    cudaGetSymbolAddress((void**)&p_B2,  g_B2);

    const int SMEM1 = 2 * (128 * 72 + 128 * 72) * 2;  // 73728
    const int SMEM2 = 2 * (128 * 72 + 64 * 72) * 2;   // 55296
    cudaFuncSetAttribute(bf16_gemm<128>,
                         cudaFuncAttributeMaxDynamicSharedMemorySize, SMEM1);
    cudaFuncSetAttribute(bf16_gemm<64>,
                         cudaFuncAttributeMaxDynamicSharedMemorySize, SMEM2);

    // side stream + events (host objects; created during capture call only)
    cudaStream_t s2;
    cudaStreamCreateWithFlags(&s2, cudaStreamNonBlocking);
    cudaEvent_t evFork, evJoin, evG1h0, evS0h0;
    cudaEventCreateWithFlags(&evFork,  cudaEventDisableTiming);
    cudaEventCreateWithFlags(&evJoin,  cudaEventDisableTiming);
    cudaEventCreateWithFlags(&evG1h0,  cudaEventDisableTiming);
    cudaEventCreateWithFlags(&evS0h0,  cudaEventDisableTiming);

    // ---- fork ----
    cudaEventRecord(evFork, 0);
    cudaStreamWaitEvent(s2, evFork, 0);

    // ---- stream B: CSR build + W2 split -> evJoin; then spmm0 half0 ----
    csr_zero<<<(N_NODES + 255) / 256, 256, 0, s2>>>();
    csr_hist<<<(2 * E_EDGES + 255) / 256, 256, 0, s2>>>(a0r, a1r);
    csr_scan<<<2, 1024, 0, s2>>>();
    csr_scatter<<<(2 * E_EDGES + 255) / 256, 256, 0, s2>>>(a0r, a0c, a0v,
                                                           a1r, a1c, a1v);
    conv_w<<<(NHID * NCLASS + 255) / 256, 256, 0, s2>>>(W2, p_B2, NHID, NCLASS);
    cudaEventRecord(evJoin, s2);

    // ---- stream A (default): x split, W1 split, GEMM1 half0 ----
    {
        long total = (long)M_PAD * (NFEAT / 4);
        conv_split_x<<<(int)((total + 255) / 256), 256>>>(x, p_A1, N_NODES, NFEAT);
        conv_w<<<(NFEAT * NHID + 255) / 256, 256>>>(W1, p_B1, NFEAT, NHID);
    }
    {
        dim3 grid(1, M_PAD / 128);
        bf16_gemm<128><<<grid, 256, SMEM1>>>(p_A1, p_B1, p_xw1,
                                             N_NODES, NHID, 3 * NFEAT, 0);
    }
    cudaEventRecord(evG1h0, 0);

    // stream B: spmm0 half0 (features [0,128)) — needs CSR (in-stream) + G1h0
    cudaStreamWaitEvent(s2, evG1h0, 0);
    spmm0_csr_half<0><<<(N_NODES + 7) / 8, 256, 0, s2>>>(b1);
    cudaEventRecord(evS0h0, s2);

    // stream A: GEMM1 half1 (columns [128,256)) — overlaps spmm0 half0
    {
        dim3 grid(1, M_PAD / 128);
        bf16_gemm<128><<<grid, 256, SMEM1>>>(p_A1, p_B1, p_xw1,
                                             N_NODES, NHID, 3 * NFEAT, 1);
    }

    // stream A: spmm0 half1 (features [128,256)) — needs CSR (evJoin) + G1h1
    cudaStreamWaitEvent(0, evJoin, 0);
    spmm0_csr_half<128><<<(N_NODES + 7) / 8, 256>>>(b1);

    // join spmm0 half0 before GEMM2 (needs full g_A2 + B2)
    cudaStreamWaitEvent(0, evS0h0, 0);

    // GEMM2: g_hw2 = relu(h+b1) @ W2 (bf16 3-term, Kp = 768)
    {
        dim3 grid(1, M_PAD / 128);
        bf16_gemm<64><<<grid, 256, SMEM2>>>(p_A2, p_B2, p_hw2,
                                            N_NODES, NCLASS, 3 * NHID, 0);
    }

    // FUSED SPMM1 + final linear + log_softmax
    spmm1_final<<<(N_NODES + 7) / 8, 256>>>(b2, LW, Lb, out);
}